// round 5
// baseline (speedup 1.0000x reference)
#include <cuda_runtime.h>
#include <cstdint>

// Problem constants (from reference)
#define E_NUM 128
#define R_NUM 65536
#define S_NUM 100000
#define ER (E_NUM * R_NUM)          // 8,388,608 floats per table

// Interleaved scratch accumulator: scratch[2*(e*R+r)+0] = delta-a,
//                                  scratch[2*(e*R+r)+1] = delta-b
// 2*ER floats = 64 MiB, static device global (no allocation).
//
// INVARIANT: g_scratch is all-zero at entry to every kernel_launch call.
//  - call #1: CUDA zero-initializes __device__ globals at module load.
//  - every call: merge_kernel reads each scratch element exactly once and
//    stores zero back, restoring the invariant for the next call/replay.
// Every call therefore performs identical work -> deterministic & graph-safe.
__device__ float g_scratch[2u * ER];

// ---------------------------------------------------------------------------
// Kernel 1: scatter-add. One thread per 4 (sample, estimator) pairs.
// int4 load of sr covers e..e+3 of the same sample; s is warp-uniform so
// da[s]/db[s] are broadcast loads. 4x red.global.add.v2.f32 — the 12.8M RED
// lanes are the hard floor (~1.29 cyc/lane spread-REDG per SM LSU).
// ---------------------------------------------------------------------------
__global__ void __launch_bounds__(256) scatter_v2x4_kernel(
        const int4* __restrict__ sr4,
        const float* __restrict__ da,
        const float* __restrict__ db) {
    int t = blockIdx.x * blockDim.x + threadIdx.x;   // [0, S*E/4)
    if (t >= S_NUM * E_NUM / 4) return;
    int e0 = (t & 31) << 2;                          // e = e0..e0+3
    int s  = t >> 5;                                 // warp-uniform
    int4 r = __ldg(sr4 + t);                         // coalesced 16B
    float va = __ldg(da + s);                        // broadcast
    float vb = __ldg(db + s);

    float* base = g_scratch + 2u * (size_t)e0 * R_NUM;
    float* p0 = base + 2u * (size_t)r.x;
    float* p1 = base + 2u * ((size_t)R_NUM + (size_t)r.y);
    float* p2 = base + 2u * (2u * (size_t)R_NUM + (size_t)r.z);
    float* p3 = base + 2u * (3u * (size_t)R_NUM + (size_t)r.w);
    asm volatile("red.global.add.v2.f32 [%0], {%1, %2};" :: "l"(p0), "f"(va), "f"(vb) : "memory");
    asm volatile("red.global.add.v2.f32 [%0], {%1, %2};" :: "l"(p1), "f"(va), "f"(vb) : "memory");
    asm volatile("red.global.add.v2.f32 [%0], {%1, %2};" :: "l"(p2), "f"(va), "f"(vb) : "memory");
    asm volatile("red.global.add.v2.f32 [%0], {%1, %2};" :: "l"(p3), "f"(va), "f"(vb) : "memory");
}

// ---------------------------------------------------------------------------
// Kernel 2: merge + reset: out[0] = a + scratch.a, out[1] = b + scratch.b
// (deinterleave), then store zeros back to scratch (restores invariant).
// scratch reads are L2-hot from the scatter; a/b cold one-shot reads use
// __ldcs; out writes use __stcs (streaming). Zero-stores dirty L2 lines whose
// writeback drains during the next replay's LSU-bound scatter (DRAM idle).
// ---------------------------------------------------------------------------
__global__ void __launch_bounds__(256) merge_reset_kernel(
        const float4* __restrict__ a,
        const float4* __restrict__ b,
        float4* __restrict__ out) {
    int i = blockIdx.x * blockDim.x + threadIdx.x;   // [0, ER/4) exact
    float4* s4 = reinterpret_cast<float4*>(g_scratch);
    float4 p0 = s4[2 * i + 0];   // {a0,b0,a1,b1}
    float4 p1 = s4[2 * i + 1];   // {a2,b2,a3,b3}
    float4 va = __ldcs(a + i);
    float4 vb = __ldcs(b + i);
    __stcs(out + i,
           make_float4(va.x + p0.x, va.y + p0.z, va.z + p1.x, va.w + p1.z));
    __stcs(out + ER / 4 + i,
           make_float4(vb.x + p0.y, vb.y + p0.w, vb.z + p1.y, vb.w + p1.w));
    // Reset scratch for the next call (keep in L2: default store policy).
    const float4 z = make_float4(0.f, 0.f, 0.f, 0.f);
    s4[2 * i + 0] = z;
    s4[2 * i + 1] = z;
}

extern "C" void kernel_launch(void* const* d_in, const int* in_sizes, int n_in,
                              void* d_out, int out_size) {
    const float* a  = (const float*)d_in[0];          // [E, R]
    const float* b  = (const float*)d_in[1];          // [E, R]
    const int*   sr = (const int*)d_in[2];            // [S, E]
    const float* da = (const float*)d_in[3];          // [S]
    const float* db = (const float*)d_in[4];          // [S]
    float* out = (float*)d_out;                       // [2, E, R]

    // Phase 1: scatter into zeroed scratch (invariant holds at entry).
    // 3.2M threads, 4 pairs each; 12500 blocks exact.
    scatter_v2x4_kernel<<<S_NUM * E_NUM / 4 / 256, 256>>>((const int4*)sr, da, db);

    // Phase 2: merge into output and reset scratch to zero.
    // 2,097,152 float4 / 256 = 8192 blocks.
    merge_reset_kernel<<<ER / 4 / 256, 256>>>((const float4*)a, (const float4*)b,
                                              (float4*)out);
}